// round 4
// baseline (speedup 1.0000x reference)
#include <cuda_runtime.h>

// Shapes (fixed by the problem)
#define BATCH 4
#define SEQ   1024
#define MODEL 1024
#define HEADS 16
#define VDIM  64
#define MROWS (BATCH*SEQ)        // 4096 GEMM rows

// Scratch (device globals — no allocations allowed)
__device__ __align__(16) float g_q [BATCH*HEADS*SEQ*VDIM];  // [bh][l][v], pre-scaled by 1/32
__device__ __align__(16) float g_kv[BATCH*HEADS*SEQ*VDIM];  // [bh][l][v]
__device__ __align__(16) float g_y [MROWS*MODEL];           // [b*L][h*v]

// ---------------------------------------------------------------------------
// SGEMM: C[4096,1024] = A[4096,1024] @ W[1024,1024]
// BM=128, BN=64, BK=16, 256 threads, 8x4 per-thread microtile.
// MODE 0: A = g_y,  write OUT (d_out)
// MODE 1: A = X,    write g_q in [bh][l][v] layout, scaled by 1/sqrt(1024)
// MODE 2: A = X,    write g_kv in [bh][l][v] layout
// ---------------------------------------------------------------------------
template<int MODE>
__global__ void __launch_bounds__(256)
gemm_kernel(const float* __restrict__ X, const float* __restrict__ W,
            float* __restrict__ OUT)
{
    const float* A = (MODE == 0) ? (const float*)g_y : X;
    const int K = MODEL, N = MODEL;

    __shared__ float As[16][132];   // [k][m], padded to kill STS conflicts
    __shared__ float Bs[16][64];    // [k][n]

    const int tid = threadIdx.x;
    const int tx = tid & 15, ty = tid >> 4;
    const int m0 = blockIdx.y * 128, n0 = blockIdx.x * 64;

    float acc[8][4];
#pragma unroll
    for (int i = 0; i < 8; i++)
#pragma unroll
        for (int j = 0; j < 4; j++) acc[i][j] = 0.f;

    for (int k0 = 0; k0 < K; k0 += 16) {
        // A tile: 128 rows x 16 k  -> As[k][m]
#pragma unroll
        for (int f = tid; f < 512; f += 256) {
            int row = f >> 2, cg = f & 3;
            float4 v = *(const float4*)(A + (size_t)(m0 + row) * K + k0 + cg * 4);
            As[cg * 4 + 0][row] = v.x;
            As[cg * 4 + 1][row] = v.y;
            As[cg * 4 + 2][row] = v.z;
            As[cg * 4 + 3][row] = v.w;
        }
        // B tile: 16 k rows x 64 n -> Bs[k][n]
        {
            int row = tid >> 4, cg = tid & 15;
            *(float4*)&Bs[row][cg * 4] =
                *(const float4*)(W + (size_t)(k0 + row) * N + n0 + cg * 4);
        }
        __syncthreads();

#pragma unroll
        for (int kk = 0; kk < 16; kk++) {
            float4 a0 = *(const float4*)&As[kk][ty * 8];
            float4 a1 = *(const float4*)&As[kk][ty * 8 + 4];
            float4 b4 = *(const float4*)&Bs[kk][tx * 4];
            float av[8] = {a0.x, a0.y, a0.z, a0.w, a1.x, a1.y, a1.z, a1.w};
            float bv[4] = {b4.x, b4.y, b4.z, b4.w};
#pragma unroll
            for (int i = 0; i < 8; i++)
#pragma unroll
                for (int j = 0; j < 4; j++) acc[i][j] += av[i] * bv[j];
        }
        __syncthreads();
    }

    // Epilogue
#pragma unroll
    for (int i = 0; i < 8; i++) {
        int row = m0 + ty * 8 + i;
        float4 r4 = make_float4(acc[i][0], acc[i][1], acc[i][2], acc[i][3]);
        if (MODE == 0) {
            *(float4*)(OUT + (size_t)row * N + n0 + tx * 4) = r4;
        } else {
            int col = n0 + tx * 4;               // 4-aligned, stays inside one head
            int h = col >> 6, v = col & 63;
            int b = row >> 10, l = row & 1023;
            float* base = (MODE == 1) ? g_q : g_kv;
            if (MODE == 1) {                     // q *= 1/sqrt(1024)
                r4.x *= 0.03125f; r4.y *= 0.03125f;
                r4.z *= 0.03125f; r4.w *= 0.03125f;
            }
            *(float4*)(base + ((size_t)((b * HEADS + h) * SEQ + l)) * VDIM + v) = r4;
        }
    }
}

// ---------------------------------------------------------------------------
// Flash attention, fp32, causal, head_dim=64.
// grid = (16 query-blocks, 64 bh). 256 threads as a 16x16 grid; each thread
// owns a 4(row) x 4(col) microtile of both S (64x64) and O (64x64).
// smem: qT[v][r] + kT[v][c] (reused as P[r][c]) + V[c][v] = exactly 48 KB.
// ---------------------------------------------------------------------------
__global__ void __launch_bounds__(256)
attn_kernel(const float* __restrict__ kw)
{
    __shared__ float qT[64][64];     // [d][r]
    __shared__ float kTps[64][64];   // [d][c], reused as P[r][c]
    __shared__ float V[64][64];      // [c][v]

    const int tid = threadIdx.x;
    const int tx = tid & 15, ty = tid >> 4;
    const int i = 15 - blockIdx.x;           // heavy diagonal blocks first
    const int bh = blockIdx.y;
    const int h = bh & (HEADS - 1);
    const int b = bh >> 4;

    // Load q tile transposed: lane-per-row mapping -> conflict-free STS
    {
        const float* qtile = g_q + ((size_t)bh * SEQ + i * 64) * VDIM;
        int r = tid & 63, c0 = tid >> 6;
#pragma unroll
        for (int it = 0; it < 4; ++it) {
            int vg = c0 + it * 4;
            float4 qv = *(const float4*)(qtile + r * 64 + vg * 4);
            qT[vg * 4 + 0][r] = qv.x;
            qT[vg * 4 + 1][r] = qv.y;
            qT[vg * 4 + 2][r] = qv.z;
            qT[vg * 4 + 3][r] = qv.w;
        }
    }

    float m[4], l[4], o[4][4];
#pragma unroll
    for (int r = 0; r < 4; r++) {
        m[r] = -1e30f; l[r] = 0.f;
#pragma unroll
        for (int c = 0; c < 4; c++) o[r][c] = 0.f;
    }

    for (int j = 0; j <= i; j++) {
        __syncthreads();   // previous iteration's P/V consumers done; qT ready

        const float* ksrc = g_kv + ((size_t)bh * SEQ + j * 64) * VDIM;
        // V tile row-major (coalesced load, conflict-free STS.128)
#pragma unroll
        for (int f = tid; f < 1024; f += 256) {
            int r = f >> 4, cg = f & 15;
            *(float4*)&V[r][cg * 4] = *(const float4*)(ksrc + r * 64 + cg * 4);
        }
        // K tile transposed + per-head learned scale (1 + kw[h][v])
        {
            int r = tid & 63, c0 = tid >> 6;
#pragma unroll
            for (int it = 0; it < 4; ++it) {
                int vg = c0 + it * 4;
                float4 kv4 = *(const float4*)(ksrc + r * 64 + vg * 4);
                float4 s4  = *(const float4*)(kw + h * 64 + vg * 4);
                kTps[vg * 4 + 0][r] = kv4.x * (1.f + s4.x);
                kTps[vg * 4 + 1][r] = kv4.y * (1.f + s4.y);
                kTps[vg * 4 + 2][r] = kv4.z * (1.f + s4.z);
                kTps[vg * 4 + 3][r] = kv4.w * (1.f + s4.w);
            }
        }
        __syncthreads();

        // S = q @ k^T  (64x64, K=64)
        float s[4][4];
#pragma unroll
        for (int r = 0; r < 4; r++)
#pragma unroll
            for (int c = 0; c < 4; c++) s[r][c] = 0.f;
#pragma unroll 16
        for (int d = 0; d < 64; d++) {
            float4 qv = *(const float4*)&qT[d][ty * 4];      // broadcast
            float4 k4 = *(const float4*)&kTps[d][tx * 4];    // conflict-free
            float qa[4] = {qv.x, qv.y, qv.z, qv.w};
            float ka[4] = {k4.x, k4.y, k4.z, k4.w};
#pragma unroll
            for (int r = 0; r < 4; r++)
#pragma unroll
                for (int c = 0; c < 4; c++) s[r][c] += qa[r] * ka[c];
        }

        // Causal mask on the diagonal block
        if (j == i) {
#pragma unroll
            for (int r = 0; r < 4; r++)
#pragma unroll
                for (int c = 0; c < 4; c++)
                    if (tx * 4 + c > ty * 4 + r) s[r][c] = -1e30f;
        }

        // Online softmax update (row groups of 16 lanes share a warp half)
#pragma unroll
        for (int r = 0; r < 4; r++) {
            float mx = fmaxf(fmaxf(s[r][0], s[r][1]), fmaxf(s[r][2], s[r][3]));
#pragma unroll
            for (int off = 8; off > 0; off >>= 1)
                mx = fmaxf(mx, __shfl_xor_sync(0xffffffffu, mx, off));
            float mn = fmaxf(m[r], mx);
            float sc = __expf(m[r] - mn);
            float rs = 0.f;
#pragma unroll
            for (int c = 0; c < 4; c++) {
                s[r][c] = __expf(s[r][c] - mn);
                rs += s[r][c];
            }
#pragma unroll
            for (int off = 8; off > 0; off >>= 1)
                rs += __shfl_xor_sync(0xffffffffu, rs, off);
            l[r] = l[r] * sc + rs;
            m[r] = mn;
#pragma unroll
            for (int c = 0; c < 4; c++) o[r][c] *= sc;
        }

        __syncthreads();   // everyone done reading kTps as K
        // Write P into the kT buffer (row-major [r][c])
#pragma unroll
        for (int r = 0; r < 4; r++)
            *(float4*)&kTps[ty * 4 + r][tx * 4] =
                make_float4(s[r][0], s[r][1], s[r][2], s[r][3]);
        __syncthreads();

        // O += P @ V
#pragma unroll 8
        for (int c = 0; c < 64; c++) {
            float4 vv = *(const float4*)&V[c][tx * 4];
#pragma unroll
            for (int r = 0; r < 4; r++) {
                float p = kTps[ty * 4 + r][c];   // broadcast
                o[r][0] += p * vv.x;
                o[r][1] += p * vv.y;
                o[r][2] += p * vv.z;
                o[r][3] += p * vv.w;
            }
        }
    }

    // Normalize and write y in [b*L][h*64+v] layout for the o-projection
#pragma unroll
    for (int r = 0; r < 4; r++) {
        float inv = 1.f / l[r];
        int row = b * SEQ + i * 64 + ty * 4 + r;
        float4 r4 = make_float4(o[r][0] * inv, o[r][1] * inv,
                                o[r][2] * inv, o[r][3] * inv);
        *(float4*)(g_y + (size_t)row * MODEL + h * 64 + tx * 4) = r4;
    }
}

// ---------------------------------------------------------------------------
extern "C" void kernel_launch(void* const* d_in, const int* in_sizes, int n_in,
                              void* d_out, int out_size)
{
    (void)in_sizes; (void)n_in; (void)out_size;
    const float* x   = (const float*)d_in[0];
    const float* w_q = (const float*)d_in[1];
    const float* w_kv= (const float*)d_in[2];
    const float* w_o = (const float*)d_in[3];
    const float* kw  = (const float*)d_in[4];
    float* out = (float*)d_out;

    dim3 ggrid(MODEL / 64, MROWS / 128);   // (16, 32)

    gemm_kernel<1><<<ggrid, 256>>>(x, w_q, nullptr);   // q  -> g_q
    gemm_kernel<2><<<ggrid, 256>>>(x, w_kv, nullptr);  // kv -> g_kv
    attn_kernel<<<dim3(16, BATCH * HEADS), 256>>>(kw); // -> g_y
    gemm_kernel<0><<<ggrid, 256>>>(nullptr, w_o, out); // y @ w_o -> out
}

// round 6
// speedup vs baseline: 1.5953x; 1.5953x over previous
#include <cuda_runtime.h>
#include <cuda_bf16.h>
#include <cstdint>

// Shapes (fixed by the problem)
#define BATCH 4
#define SEQ   1024
#define MODEL 1024
#define HEADS 16
#define VDIM  64
#define MROWS (BATCH*SEQ)        // 4096 GEMM rows

// Scratch (device globals — no allocations allowed)
__device__ __align__(16) float    g_q [BATCH*HEADS*SEQ*VDIM]; // [bh][l][v], pre-scaled
__device__ __align__(16) float    g_kv[BATCH*HEADS*SEQ*VDIM]; // [bh][l][v]
__device__ __align__(16) float    g_y [MROWS*MODEL];          // [b*L][h*v]
__device__ __align__(16) uint16_t g_wb_hi[3][MODEL*MODEL];    // W^T bf16 hi, [n][k]
__device__ __align__(16) uint16_t g_wb_lo[3][MODEL*MODEL];    // W^T bf16 lo, [n][k]

// ---------------------------------------------------------------------------
// Helpers (family-portable PTX only: ldmatrix + mma.sync, sm_80-class)
// ---------------------------------------------------------------------------
__device__ __forceinline__ uint32_t smem_u32(const void* p) {
    uint32_t a;
    asm("{ .reg .u64 t; cvta.to.shared.u64 t, %1; cvt.u32.u64 %0, t; }"
        : "=r"(a) : "l"(p));
    return a;
}
// pack two f32 -> bf16x2 (e0 = low half)
__device__ __forceinline__ uint32_t bf16x2(float e0, float e1) {
    uint32_t r;
    asm("cvt.rn.bf16x2.f32 %0, %1, %2;" : "=r"(r) : "f"(e1), "f"(e0));
    return r;
}
__device__ __forceinline__ void bsplit(float a, float& h, float& l) {
    h = __bfloat162float(__float2bfloat16_rn(a));
    l = a - h;                                   // packed rn later = bf16 lo
}
#define SWB(b) ((b) ^ (((b) >> 3) & 0x70))       // SW128 XOR swizzle (128B rows)

#define LDSM4(r0, r1, r2, r3, addr) \
    asm volatile("ldmatrix.sync.aligned.m8n8.x4.shared.b16 {%0,%1,%2,%3}, [%4];" \
        : "=r"(r0), "=r"(r1), "=r"(r2), "=r"(r3) : "r"(addr))

#define MMA16816(C, A, B) \
    asm volatile("mma.sync.aligned.m16n8k16.row.col.f32.bf16.bf16.f32 " \
        "{%0,%1,%2,%3},{%4,%5,%6,%7},{%8,%9},{%0,%1,%2,%3};" \
        : "+f"((C)[0]), "+f"((C)[1]), "+f"((C)[2]), "+f"((C)[3]) \
        : "r"((A)[0]), "r"((A)[1]), "r"((A)[2]), "r"((A)[3]), \
          "r"((B)[0]), "r"((B)[1]))

// ---------------------------------------------------------------------------
// Weight transpose + bf16 hi/lo split: W[k][n] -> Wt_hi/lo[n][k] (3 weights)
// grid (32, 32, 3), 256 threads, 32x32 tiles.
// ---------------------------------------------------------------------------
__global__ void __launch_bounds__(256)
wsplit_kernel(const float* __restrict__ w0, const float* __restrict__ w1,
              const float* __restrict__ w2)
{
    __shared__ float s[32][33];
    const int z = blockIdx.z;
    const float* src = (z == 0) ? w0 : (z == 1) ? w1 : w2;
    uint16_t* dh = g_wb_hi[z];
    uint16_t* dl = g_wb_lo[z];
    const int kt = blockIdx.x * 32, nt = blockIdx.y * 32;
    const int f = threadIdx.x;
    const int r = f >> 3, c4 = f & 7;

    float4 v = *(const float4*)(src + (size_t)(kt + r) * MODEL + nt + c4 * 4);
    s[r][c4 * 4 + 0] = v.x; s[r][c4 * 4 + 1] = v.y;
    s[r][c4 * 4 + 2] = v.z; s[r][c4 * 4 + 3] = v.w;
    __syncthreads();

    float h[4], l[4];
#pragma unroll
    for (int q = 0; q < 4; q++) bsplit(s[c4 * 4 + q][r], h[q], l[q]);

    uint2 H = make_uint2(bf16x2(h[0], h[1]), bf16x2(h[2], h[3]));
    uint2 L = make_uint2(bf16x2(l[0], l[1]), bf16x2(l[2], l[3]));
    size_t off = (size_t)(nt + r) * MODEL + kt + c4 * 4;
    *(uint2*)(dh + off) = H;
    *(uint2*)(dl + off) = L;
}

// ---------------------------------------------------------------------------
// 3xBF16 error-compensated GEMM via mma.sync.m16n8k16 (HMMA).
// C[4096,1024] = A[4096,1024] @ W[1024,1024].
// CTA tile 128(M) x 128(N) x 64(K). 256 thr = 8 warps (2 along M x 4 along N),
// warp tile 64x32 = 4 m16-tiles x 4 n8-tiles.
// Passes: A_hi*B_hi + A_hi*B_lo + A_lo*B_hi  (fp32 accum).
// MODE 0: A=g_y, W=wT[2] -> d_out.  MODE 1: A=x, W=wT[0] -> g_q (x 1/32).
// MODE 2: A=x, W=wT[1] -> g_kv.
// ---------------------------------------------------------------------------
#define SA_HI 0
#define SA_LO 16384
#define SB_HI 32768
#define SB_LO 49152
#define GEMM_SMEM 65536

template<int MODE>
__global__ void __launch_bounds__(256)
gemm_bf16(const float* __restrict__ Aext, float* __restrict__ OUT)
{
    extern __shared__ __align__(1024) char smem[];
    const uint32_t sb = smem_u32(smem);

    const float* A  = (MODE == 0) ? (const float*)g_y : Aext;
    const int widx  = (MODE == 1) ? 0 : (MODE == 2) ? 1 : 2;
    const uint16_t* __restrict__ Bh = g_wb_hi[widx];
    const uint16_t* __restrict__ Bl = g_wb_lo[widx];

    const int tid  = threadIdx.x;
    const int lane = tid & 31, wid = tid >> 5;
    const int warp_m = wid & 1;          // 0..1, 64 rows each
    const int warp_n = wid >> 1;         // 0..3, 32 cols each
    const int m0 = blockIdx.y * 128, n0 = blockIdx.x * 128;

    // per-lane ldmatrix address components
    const int a_r  = lane & 15;                       // A: row within 16-tile
    const int a_kb = (lane >> 4) * 16;                // A: k byte offset (0/16)
    const int b_r  = (lane & 7) | ((lane & 16) >> 1); // B: n row within 16
    const int b_kb = (lane & 8) * 2;                  // B: k byte offset (0/16)

    float c[4][4][4];
#pragma unroll
    for (int mt = 0; mt < 4; mt++)
#pragma unroll
        for (int nt = 0; nt < 4; nt++)
#pragma unroll
            for (int q = 0; q < 4; q++) c[mt][nt][q] = 0.f;

    for (int kc = 0; kc < 16; kc++) {
        if (kc) __syncthreads();   // previous compute done before overwrite

        // A tile [128 m][64 k] fp32 -> bf16 hi/lo, swizzled 128B rows
#pragma unroll
        for (int i = 0; i < 8; i++) {
            int e = (tid + i * 256) * 4;
            int row = e >> 6, k0 = e & 63;
            float4 v = *(const float4*)(A + (size_t)(m0 + row) * MODEL + kc * 64 + k0);
            float h0, h1, h2, h3, l0, l1, l2, l3;
            bsplit(v.x, h0, l0); bsplit(v.y, h1, l1);
            bsplit(v.z, h2, l2); bsplit(v.w, h3, l3);
            uint32_t off = SWB((uint32_t)(row * 128 + k0 * 2));
            *(uint2*)(smem + SA_HI + off) = make_uint2(bf16x2(h0, h1), bf16x2(h2, h3));
            *(uint2*)(smem + SA_LO + off) = make_uint2(bf16x2(l0, l1), bf16x2(l2, l3));
        }
        // B tile [128 n][64 k] bf16 hi/lo (pre-split), swizzled
#pragma unroll
        for (int i = 0; i < 4; i++) {
            int e = (tid + i * 256) * 8;
            int row = e >> 6, kk = e & 63;
            size_t g = (size_t)(n0 + row) * MODEL + kc * 64 + kk;
            uint4 h4 = *(const uint4*)(Bh + g);
            uint4 l4 = *(const uint4*)(Bl + g);
            uint32_t off = SWB((uint32_t)(row * 128 + kk * 2));
            *(uint4*)(smem + SB_HI + off) = h4;
            *(uint4*)(smem + SB_LO + off) = l4;
        }
        __syncthreads();

#pragma unroll
        for (int p = 0; p < 3; p++) {
            const uint32_t Ab = sb + ((p == 2) ? SA_LO : SA_HI);
            const uint32_t Bb = sb + ((p == 1) ? SB_LO : SB_HI);
#pragma unroll
            for (int ks = 0; ks < 4; ks++) {
                uint32_t a[4][4], b[4][2];
#pragma unroll
                for (int mt = 0; mt < 4; mt++) {
                    uint32_t ad = Ab + SWB((uint32_t)(
                        (warp_m * 64 + mt * 16 + a_r) * 128 + ks * 32 + a_kb));
                    LDSM4(a[mt][0], a[mt][1], a[mt][2], a[mt][3], ad);
                }
#pragma unroll
                for (int bt = 0; bt < 2; bt++) {
                    uint32_t bd = Bb + SWB((uint32_t)(
                        (warp_n * 32 + bt * 16 + b_r) * 128 + ks * 32 + b_kb));
                    LDSM4(b[2 * bt][0], b[2 * bt][1],
                          b[2 * bt + 1][0], b[2 * bt + 1][1], bd);
                }
#pragma unroll
                for (int mt = 0; mt < 4; mt++)
#pragma unroll
                    for (int nt = 0; nt < 4; nt++)
                        MMA16816(c[mt][nt], a[mt], b[nt]);
            }
        }
    }

    // Epilogue: c0,c1 -> (row, col..col+1); c2,c3 -> (row+8, same cols)
    const int gr = lane >> 2, gc = (lane & 3) * 2;
#pragma unroll
    for (int mt = 0; mt < 4; mt++) {
#pragma unroll
        for (int nt = 0; nt < 4; nt++) {
            int row = m0 + warp_m * 64 + mt * 16 + gr;
            int col = n0 + warp_n * 32 + nt * 8 + gc;
#pragma unroll
            for (int half = 0; half < 2; half++) {
                int rr = row + half * 8;
                float2 r2 = make_float2(c[mt][nt][half * 2], c[mt][nt][half * 2 + 1]);
                if (MODE == 0) {
                    *(float2*)(OUT + (size_t)rr * MODEL + col) = r2;
                } else {
                    if (MODE == 1) { r2.x *= 0.03125f; r2.y *= 0.03125f; }
                    int h = col >> 6, v = col & 63;
                    int b = rr >> 10, l = rr & 1023;
                    float* base = (MODE == 1) ? g_q : g_kv;
                    *(float2*)(base + ((size_t)((b * HEADS + h) * SEQ + l)) * VDIM + v) = r2;
                }
            }
        }
    }
}

// ---------------------------------------------------------------------------
// Flash attention, fp32, causal, head_dim=64 (unchanged, known-good).
// ---------------------------------------------------------------------------
__global__ void __launch_bounds__(256)
attn_kernel(const float* __restrict__ kw)
{
    __shared__ float qT[64][64];     // [d][r]
    __shared__ float kTps[64][64];   // [d][c], reused as P[r][c]
    __shared__ float V[64][64];      // [c][v]

    const int tid = threadIdx.x;
    const int tx = tid & 15, ty = tid >> 4;
    const int i = 15 - blockIdx.x;           // heavy diagonal blocks first
    const int bh = blockIdx.y;
    const int h = bh & (HEADS - 1);
    const int b = bh >> 4;

    {
        const float* qtile = g_q + ((size_t)bh * SEQ + i * 64) * VDIM;
        int r = tid & 63, c0 = tid >> 6;
#pragma unroll
        for (int it = 0; it < 4; ++it) {
            int vg = c0 + it * 4;
            float4 qv = *(const float4*)(qtile + r * 64 + vg * 4);
            qT[vg * 4 + 0][r] = qv.x;
            qT[vg * 4 + 1][r] = qv.y;
            qT[vg * 4 + 2][r] = qv.z;
            qT[vg * 4 + 3][r] = qv.w;
        }
    }

    float m[4], l[4], o[4][4];
#pragma unroll
    for (int r = 0; r < 4; r++) {
        m[r] = -1e30f; l[r] = 0.f;
#pragma unroll
        for (int c = 0; c < 4; c++) o[r][c] = 0.f;
    }

    for (int j = 0; j <= i; j++) {
        __syncthreads();

        const float* ksrc = g_kv + ((size_t)bh * SEQ + j * 64) * VDIM;
#pragma unroll
        for (int f = tid; f < 1024; f += 256) {
            int r = f >> 4, cg = f & 15;
            *(float4*)&V[r][cg * 4] = *(const float4*)(ksrc + r * 64 + cg * 4);
        }
        {
            int r = tid & 63, c0 = tid >> 6;
#pragma unroll
            for (int it = 0; it < 4; ++it) {
                int vg = c0 + it * 4;
                float4 kv4 = *(const float4*)(ksrc + r * 64 + vg * 4);
                float4 s4  = *(const float4*)(kw + h * 64 + vg * 4);
                kTps[vg * 4 + 0][r] = kv4.x * (1.f + s4.x);
                kTps[vg * 4 + 1][r] = kv4.y * (1.f + s4.y);
                kTps[vg * 4 + 2][r] = kv4.z * (1.f + s4.z);
                kTps[vg * 4 + 3][r] = kv4.w * (1.f + s4.w);
            }
        }
        __syncthreads();

        float s[4][4];
#pragma unroll
        for (int r = 0; r < 4; r++)
#pragma unroll
            for (int c = 0; c < 4; c++) s[r][c] = 0.f;
#pragma unroll 16
        for (int d = 0; d < 64; d++) {
            float4 qv = *(const float4*)&qT[d][ty * 4];
            float4 k4 = *(const float4*)&kTps[d][tx * 4];
            float qa[4] = {qv.x, qv.y, qv.z, qv.w};
            float ka[4] = {k4.x, k4.y, k4.z, k4.w};
#pragma unroll
            for (int r = 0; r < 4; r++)
#pragma unroll
                for (int c = 0; c < 4; c++) s[r][c] += qa[r] * ka[c];
        }

        if (j == i) {
#pragma unroll
            for (int r = 0; r < 4; r++)
#pragma unroll
                for (int c = 0; c < 4; c++)
                    if (tx * 4 + c > ty * 4 + r) s[r][c] = -1e30f;
        }

#pragma unroll
        for (int r = 0; r < 4; r++) {
            float mx = fmaxf(fmaxf(s[r][0], s[r][1]), fmaxf(s[r][2], s[r][3]));
#pragma unroll
            for (int off = 8; off > 0; off >>= 1)
                mx = fmaxf(mx, __shfl_xor_sync(0xffffffffu, mx, off));
            float mn = fmaxf(m[r], mx);
            float sc = __expf(m[r] - mn);
            float rs = 0.f;
#pragma unroll
            for (int c = 0; c < 4; c++) {
                s[r][c] = __expf(s[r][c] - mn);
                rs += s[r][c];
            }
#pragma unroll
            for (int off = 8; off > 0; off >>= 1)
                rs += __shfl_xor_sync(0xffffffffu, rs, off);
            l[r] = l[r] * sc + rs;
            m[r] = mn;
#pragma unroll
            for (int c = 0; c < 4; c++) o[r][c] *= sc;
        }

        __syncthreads();
#pragma unroll
        for (int r = 0; r < 4; r++)
            *(float4*)&kTps[ty * 4 + r][tx * 4] =
                make_float4(s[r][0], s[r][1], s[r][2], s[r][3]);
        __syncthreads();

#pragma unroll 8
        for (int c = 0; c < 64; c++) {
            float4 vv = *(const float4*)&V[c][tx * 4];
#pragma unroll
            for (int r = 0; r < 4; r++) {
                float p = kTps[ty * 4 + r][c];
                o[r][0] += p * vv.x;
                o[r][1] += p * vv.y;
                o[r][2] += p * vv.z;
                o[r][3] += p * vv.w;
            }
        }
    }

#pragma unroll
    for (int r = 0; r < 4; r++) {
        float inv = 1.f / l[r];
        int row = b * SEQ + i * 64 + ty * 4 + r;
        float4 r4 = make_float4(o[r][0] * inv, o[r][1] * inv,
                                o[r][2] * inv, o[r][3] * inv);
        *(float4*)(g_y + (size_t)row * MODEL + h * 64 + tx * 4) = r4;
    }
}

// ---------------------------------------------------------------------------
extern "C" void kernel_launch(void* const* d_in, const int* in_sizes, int n_in,
                              void* d_out, int out_size)
{
    (void)in_sizes; (void)n_in; (void)out_size;
    const float* x    = (const float*)d_in[0];
    const float* w_q  = (const float*)d_in[1];
    const float* w_kv = (const float*)d_in[2];
    const float* w_o  = (const float*)d_in[3];
    const float* kw   = (const float*)d_in[4];
    float* out = (float*)d_out;

    cudaFuncSetAttribute(gemm_bf16<0>, cudaFuncAttributeMaxDynamicSharedMemorySize, GEMM_SMEM);
    cudaFuncSetAttribute(gemm_bf16<1>, cudaFuncAttributeMaxDynamicSharedMemorySize, GEMM_SMEM);
    cudaFuncSetAttribute(gemm_bf16<2>, cudaFuncAttributeMaxDynamicSharedMemorySize, GEMM_SMEM);

    dim3 ggrid(MODEL / 128, MROWS / 128);                    // (8, 32)

    wsplit_kernel<<<dim3(32, 32, 3), 256>>>(w_q, w_kv, w_o); // W^T hi/lo bf16
    gemm_bf16<1><<<ggrid, 256, GEMM_SMEM>>>(x, nullptr);     // q  -> g_q
    gemm_bf16<2><<<ggrid, 256, GEMM_SMEM>>>(x, nullptr);     // kv -> g_kv
    attn_kernel<<<dim3(16, BATCH * HEADS), 256>>>(kw);       // -> g_y
    gemm_bf16<0><<<ggrid, 256, GEMM_SMEM>>>(nullptr, out);   // y @ w_o -> out
}

// round 10
// speedup vs baseline: 2.2673x; 1.4212x over previous
#include <cuda_runtime.h>
#include <cuda_bf16.h>
#include <cstdint>

// Shapes (fixed by the problem)
#define BATCH 4
#define SEQ   1024
#define MODEL 1024
#define HEADS 16
#define VDIM  64
#define MROWS (BATCH*SEQ)        // 4096 GEMM rows

// Scratch (device globals — no allocations allowed)
__device__ __align__(16) float    g_q [BATCH*HEADS*SEQ*VDIM]; // [bh][l][v], pre-scaled
__device__ __align__(16) float    g_kv[BATCH*HEADS*SEQ*VDIM]; // [bh][l][v]
__device__ __align__(16) float    g_y [MROWS*MODEL];          // [b*L][h*v]
__device__ __align__(16) uint16_t g_wb_hi[3][MODEL*MODEL];    // W^T bf16 hi, [n][k]
__device__ __align__(16) uint16_t g_wb_lo[3][MODEL*MODEL];    // W^T bf16 lo, [n][k]

// ---------------------------------------------------------------------------
// Helpers (family-portable PTX only: ldmatrix + mma.sync, sm_80-class)
// ---------------------------------------------------------------------------
__device__ __forceinline__ uint32_t smem_u32(const void* p) {
    uint32_t a;
    asm("{ .reg .u64 t; cvta.to.shared.u64 t, %1; cvt.u32.u64 %0, t; }"
        : "=r"(a) : "l"(p));
    return a;
}
// pack two f32 -> bf16x2 (e0 = low half)
__device__ __forceinline__ uint32_t bf16x2(float e0, float e1) {
    uint32_t r;
    asm("cvt.rn.bf16x2.f32 %0, %1, %2;" : "=r"(r) : "f"(e1), "f"(e0));
    return r;
}
__device__ __forceinline__ void bsplit(float a, float& h, float& l) {
    h = __bfloat162float(__float2bfloat16_rn(a));
    l = a - h;
}
__device__ __forceinline__ float bhi(float a) {
    return __bfloat162float(__float2bfloat16_rn(a));
}
__device__ __forceinline__ uint16_t b16(float f) {
    __nv_bfloat16 t = __float2bfloat16_rn(f);
    return *reinterpret_cast<uint16_t*>(&t);
}
#define SWB(b) ((b) ^ (((b) >> 3) & 0x70))       // SW128 XOR swizzle (128B rows)

#define LDSM4(r0, r1, r2, r3, addr) \
    asm volatile("ldmatrix.sync.aligned.m8n8.x4.shared.b16 {%0,%1,%2,%3}, [%4];" \
        : "=r"(r0), "=r"(r1), "=r"(r2), "=r"(r3) : "r"(addr))

#define MMA16816(C, A, B) \
    asm volatile("mma.sync.aligned.m16n8k16.row.col.f32.bf16.bf16.f32 " \
        "{%0,%1,%2,%3},{%4,%5,%6,%7},{%8,%9},{%0,%1,%2,%3};" \
        : "+f"((C)[0]), "+f"((C)[1]), "+f"((C)[2]), "+f"((C)[3]) \
        : "r"((A)[0]), "r"((A)[1]), "r"((A)[2]), "r"((A)[3]), \
          "r"((B)[0]), "r"((B)[1]))

// ---------------------------------------------------------------------------
// Weight transpose + bf16 hi/lo split: W[k][n] -> Wt_hi/lo[n][k] (3 weights)
// ---------------------------------------------------------------------------
__global__ void __launch_bounds__(256)
wsplit_kernel(const float* __restrict__ w0, const float* __restrict__ w1,
              const float* __restrict__ w2)
{
    __shared__ float s[32][33];
    const int z = blockIdx.z;
    const float* src = (z == 0) ? w0 : (z == 1) ? w1 : w2;
    uint16_t* dh = g_wb_hi[z];
    uint16_t* dl = g_wb_lo[z];
    const int kt = blockIdx.x * 32, nt = blockIdx.y * 32;
    const int f = threadIdx.x;
    const int r = f >> 3, c4 = f & 7;

    float4 v = *(const float4*)(src + (size_t)(kt + r) * MODEL + nt + c4 * 4);
    s[r][c4 * 4 + 0] = v.x; s[r][c4 * 4 + 1] = v.y;
    s[r][c4 * 4 + 2] = v.z; s[r][c4 * 4 + 3] = v.w;
    __syncthreads();

    float h[4], l[4];
#pragma unroll
    for (int q = 0; q < 4; q++) bsplit(s[c4 * 4 + q][r], h[q], l[q]);

    uint2 H = make_uint2(bf16x2(h[0], h[1]), bf16x2(h[2], h[3]));
    uint2 L = make_uint2(bf16x2(l[0], l[1]), bf16x2(l[2], l[3]));
    size_t off = (size_t)(nt + r) * MODEL + kt + c4 * 4;
    *(uint2*)(dh + off) = H;
    *(uint2*)(dl + off) = L;
}

// ---------------------------------------------------------------------------
// 3xBF16 error-compensated GEMM via mma.sync.m16n8k16 (unchanged, passed R6).
// ---------------------------------------------------------------------------
#define SA_HI 0
#define SA_LO 16384
#define SB_HI 32768
#define SB_LO 49152
#define GEMM_SMEM 65536

template<int MODE>
__global__ void __launch_bounds__(256)
gemm_bf16(const float* __restrict__ Aext, float* __restrict__ OUT)
{
    extern __shared__ __align__(1024) char smem[];
    const uint32_t sb = smem_u32(smem);

    const float* A  = (MODE == 0) ? (const float*)g_y : Aext;
    const int widx  = (MODE == 1) ? 0 : (MODE == 2) ? 1 : 2;
    const uint16_t* __restrict__ Bh = g_wb_hi[widx];
    const uint16_t* __restrict__ Bl = g_wb_lo[widx];

    const int tid  = threadIdx.x;
    const int lane = tid & 31, wid = tid >> 5;
    const int warp_m = wid & 1;
    const int warp_n = wid >> 1;
    const int m0 = blockIdx.y * 128, n0 = blockIdx.x * 128;

    const int a_r  = lane & 15;
    const int a_kb = (lane >> 4) * 16;
    const int b_r  = (lane & 7) | ((lane & 16) >> 1);
    const int b_kb = (lane & 8) * 2;

    float c[4][4][4];
#pragma unroll
    for (int mt = 0; mt < 4; mt++)
#pragma unroll
        for (int nt = 0; nt < 4; nt++)
#pragma unroll
            for (int q = 0; q < 4; q++) c[mt][nt][q] = 0.f;

    for (int kc = 0; kc < 16; kc++) {
        if (kc) __syncthreads();

#pragma unroll
        for (int i = 0; i < 8; i++) {
            int e = (tid + i * 256) * 4;
            int row = e >> 6, k0 = e & 63;
            float4 v = *(const float4*)(A + (size_t)(m0 + row) * MODEL + kc * 64 + k0);
            float h0, h1, h2, h3, l0, l1, l2, l3;
            bsplit(v.x, h0, l0); bsplit(v.y, h1, l1);
            bsplit(v.z, h2, l2); bsplit(v.w, h3, l3);
            uint32_t off = SWB((uint32_t)(row * 128 + k0 * 2));
            *(uint2*)(smem + SA_HI + off) = make_uint2(bf16x2(h0, h1), bf16x2(h2, h3));
            *(uint2*)(smem + SA_LO + off) = make_uint2(bf16x2(l0, l1), bf16x2(l2, l3));
        }
#pragma unroll
        for (int i = 0; i < 4; i++) {
            int e = (tid + i * 256) * 8;
            int row = e >> 6, kk = e & 63;
            size_t g = (size_t)(n0 + row) * MODEL + kc * 64 + kk;
            uint4 h4 = *(const uint4*)(Bh + g);
            uint4 l4 = *(const uint4*)(Bl + g);
            uint32_t off = SWB((uint32_t)(row * 128 + kk * 2));
            *(uint4*)(smem + SB_HI + off) = h4;
            *(uint4*)(smem + SB_LO + off) = l4;
        }
        __syncthreads();

#pragma unroll
        for (int p = 0; p < 3; p++) {
            const uint32_t Ab = sb + ((p == 2) ? SA_LO : SA_HI);
            const uint32_t Bb = sb + ((p == 1) ? SB_LO : SB_HI);
#pragma unroll
            for (int ks = 0; ks < 4; ks++) {
                uint32_t a[4][4], b[4][2];
#pragma unroll
                for (int mt = 0; mt < 4; mt++) {
                    uint32_t ad = Ab + SWB((uint32_t)(
                        (warp_m * 64 + mt * 16 + a_r) * 128 + ks * 32 + a_kb));
                    LDSM4(a[mt][0], a[mt][1], a[mt][2], a[mt][3], ad);
                }
#pragma unroll
                for (int bt = 0; bt < 2; bt++) {
                    uint32_t bd = Bb + SWB((uint32_t)(
                        (warp_n * 32 + bt * 16 + b_r) * 128 + ks * 32 + b_kb));
                    LDSM4(b[2 * bt][0], b[2 * bt][1],
                          b[2 * bt + 1][0], b[2 * bt + 1][1], bd);
                }
#pragma unroll
                for (int mt = 0; mt < 4; mt++)
#pragma unroll
                    for (int nt = 0; nt < 4; nt++)
                        MMA16816(c[mt][nt], a[mt], b[nt]);
            }
        }
    }

    const int gr = lane >> 2, gc = (lane & 3) * 2;
#pragma unroll
    for (int mt = 0; mt < 4; mt++) {
#pragma unroll
        for (int nt = 0; nt < 4; nt++) {
            int row = m0 + warp_m * 64 + mt * 16 + gr;
            int col = n0 + warp_n * 32 + nt * 8 + gc;
#pragma unroll
            for (int half = 0; half < 2; half++) {
                int rr = row + half * 8;
                float2 r2 = make_float2(c[mt][nt][half * 2], c[mt][nt][half * 2 + 1]);
                if (MODE == 0) {
                    *(float2*)(OUT + (size_t)rr * MODEL + col) = r2;
                } else {
                    if (MODE == 1) { r2.x *= 0.03125f; r2.y *= 0.03125f; }
                    int h = col >> 6, v = col & 63;
                    int b = rr >> 10, l = rr & 1023;
                    float* base = (MODE == 1) ? g_q : g_kv;
                    *(float2*)(base + ((size_t)((b * HEADS + h) * SEQ + l)) * VDIM + v) = r2;
                }
            }
        }
    }
}

// ---------------------------------------------------------------------------
// Tensor-core flash attention, causal, head_dim=64, 3xBF16 compensation.
// CTA = (bh, 64-query block). 4 warps x 16 rows. Per 64-key tile:
//   S = QK^T (3 passes), fragment-level online softmax, P packed from C-frags
//   directly into A-frags (hi + lo residual), O += P V^T (3 passes).
// smem: Q,K (scaled), V^T each hi/lo bf16 [64][64] = 48KB exactly.
// ---------------------------------------------------------------------------
__global__ void __launch_bounds__(128)
attn_tc(const float* __restrict__ kw_g)
{
    __shared__ uint16_t Qh[4096], Ql[4096];   // [qrow][d]
    __shared__ uint16_t Kh[4096], Kl[4096];   // [key][d]  (scaled by 1+kw)
    __shared__ uint16_t Vh[4096], Vl[4096];   // [v][key]  (V^T)

    const int tid = threadIdx.x, lane = tid & 31, warp = tid >> 5;
    const int i  = 15 - blockIdx.x;          // heavy diagonal blocks first
    const int bh = blockIdx.y;
    const int h  = bh & (HEADS - 1);
    const int b  = bh >> 4;

    const int a_r  = lane & 15;
    const int a_kb = (lane >> 4) * 16;
    const int b_r  = (lane & 7) | ((lane & 16) >> 1);
    const int b_kb = (lane & 8) * 2;

    // ---- Q tile load + hi/lo split (once) ----
    {
        const float* qsrc = g_q + ((size_t)bh * SEQ + i * 64) * VDIM;
#pragma unroll
        for (int it = 0; it < 8; it++) {
            int f = tid + it * 128;
            int row = f >> 4, c4 = f & 15;
            float4 v = *(const float4*)(qsrc + row * 64 + c4 * 4);
            float h0, h1, h2, h3, l0, l1, l2, l3;
            bsplit(v.x, h0, l0); bsplit(v.y, h1, l1);
            bsplit(v.z, h2, l2); bsplit(v.w, h3, l3);
            uint32_t off = SWB((uint32_t)(row * 128 + c4 * 8));
            *(uint2*)((char*)Qh + off) = make_uint2(bf16x2(h0, h1), bf16x2(h2, h3));
            *(uint2*)((char*)Ql + off) = make_uint2(bf16x2(l0, l1), bf16x2(l2, l3));
        }
    }
    __syncthreads();

    // ---- preload Q A-fragments (resident across the j loop) ----
    uint32_t qh[4][4], ql[4][4];
    {
        const uint32_t qhb = smem_u32(Qh), qlb = smem_u32(Ql);
#pragma unroll
        for (int ks = 0; ks < 4; ks++) {
            uint32_t off = SWB((uint32_t)((warp * 16 + a_r) * 128 + ks * 32 + a_kb));
            LDSM4(qh[ks][0], qh[ks][1], qh[ks][2], qh[ks][3], qhb + off);
            LDSM4(ql[ks][0], ql[ks][1], ql[ks][2], ql[ks][3], qlb + off);
        }
    }

    float o[8][4];
#pragma unroll
    for (int vt = 0; vt < 8; vt++)
#pragma unroll
        for (int q = 0; q < 4; q++) o[vt][q] = 0.f;
    float mx0 = -1e30f, mx1 = -1e30f, sum0 = 0.f, sum1 = 0.f;

    const uint32_t khb = smem_u32(Kh), klb = smem_u32(Kl);
    const uint32_t vhb = smem_u32(Vh), vlb = smem_u32(Vl);

    for (int j = 0; j <= i; j++) {
        if (j) __syncthreads();   // prior reads of K/V smem complete
        const float* ksrc = g_kv + ((size_t)bh * SEQ + j * 64) * VDIM;

        // K tile: scaled by (1+kw), hi/lo split, K-major rows (coalesced)
#pragma unroll
        for (int it = 0; it < 8; it++) {
            int f = tid + it * 128;
            int row = f >> 4, c4 = f & 15;
            float4 v  = *(const float4*)(ksrc + row * 64 + c4 * 4);
            float4 w4 = *(const float4*)(kw_g + h * 64 + c4 * 4);
            float h0, h1, h2, h3, l0, l1, l2, l3;
            bsplit(v.x * (1.f + w4.x), h0, l0);
            bsplit(v.y * (1.f + w4.y), h1, l1);
            bsplit(v.z * (1.f + w4.z), h2, l2);
            bsplit(v.w * (1.f + w4.w), h3, l3);
            uint32_t off = SWB((uint32_t)(row * 128 + c4 * 8));
            *(uint2*)((char*)Kh + off) = make_uint2(bf16x2(h0, h1), bf16x2(h2, h3));
            *(uint2*)((char*)Kl + off) = make_uint2(bf16x2(l0, l1), bf16x2(l2, l3));
        }
        // V^T tile: unscaled, transposed (L1-hot re-read), hi/lo split
        {
            int r = tid & 63, hf = tid >> 6;
#pragma unroll
            for (int it = 0; it < 8; it++) {
                int v0 = hf * 32 + it * 4;
                float4 v = *(const float4*)(ksrc + r * 64 + v0);
                const float* vp = &v.x;
#pragma unroll
                for (int q = 0; q < 4; q++) {
                    float hi, lo; bsplit(vp[q], hi, lo);
                    uint32_t off = SWB((uint32_t)((v0 + q) * 128 + r * 2));
                    *(uint16_t*)((char*)Vh + off) = b16(hi);
                    *(uint16_t*)((char*)Vl + off) = b16(lo);
                }
            }
        }
        __syncthreads();

        // ---- S = Q K^T : 3-pass compensation ----
        float sacc[8][4];
#pragma unroll
        for (int nt = 0; nt < 8; nt++)
#pragma unroll
            for (int q = 0; q < 4; q++) sacc[nt][q] = 0.f;

#pragma unroll
        for (int ks = 0; ks < 4; ks++) {
            uint32_t kf[8][2];
#pragma unroll
            for (int g = 0; g < 4; g++) {
                uint32_t off = SWB((uint32_t)((g * 16 + b_r) * 128 + ks * 32 + b_kb));
                LDSM4(kf[2 * g][0], kf[2 * g][1], kf[2 * g + 1][0], kf[2 * g + 1][1],
                      khb + off);
            }
#pragma unroll
            for (int nt = 0; nt < 8; nt++) MMA16816(sacc[nt], qh[ks], kf[nt]);
#pragma unroll
            for (int nt = 0; nt < 8; nt++) MMA16816(sacc[nt], ql[ks], kf[nt]);
#pragma unroll
            for (int g = 0; g < 4; g++) {
                uint32_t off = SWB((uint32_t)((g * 16 + b_r) * 128 + ks * 32 + b_kb));
                LDSM4(kf[2 * g][0], kf[2 * g][1], kf[2 * g + 1][0], kf[2 * g + 1][1],
                      klb + off);
            }
#pragma unroll
            for (int nt = 0; nt < 8; nt++) MMA16816(sacc[nt], qh[ks], kf[nt]);
        }

        // ---- causal mask on diagonal tile ----
        if (j == i) {
            int r0 = warp * 16 + (lane >> 2);
            int c0 = (lane & 3) * 2;
#pragma unroll
            for (int nt = 0; nt < 8; nt++) {
                int col = nt * 8 + c0;
                if (col     > r0)     sacc[nt][0] = -1e30f;
                if (col + 1 > r0)     sacc[nt][1] = -1e30f;
                if (col     > r0 + 8) sacc[nt][2] = -1e30f;
                if (col + 1 > r0 + 8) sacc[nt][3] = -1e30f;
            }
        }

        // ---- online softmax in fragment registers ----
        float rmax0 = -1e30f, rmax1 = -1e30f;
#pragma unroll
        for (int nt = 0; nt < 8; nt++) {
            rmax0 = fmaxf(rmax0, fmaxf(sacc[nt][0], sacc[nt][1]));
            rmax1 = fmaxf(rmax1, fmaxf(sacc[nt][2], sacc[nt][3]));
        }
        rmax0 = fmaxf(rmax0, __shfl_xor_sync(0xffffffffu, rmax0, 1));
        rmax0 = fmaxf(rmax0, __shfl_xor_sync(0xffffffffu, rmax0, 2));
        rmax1 = fmaxf(rmax1, __shfl_xor_sync(0xffffffffu, rmax1, 1));
        rmax1 = fmaxf(rmax1, __shfl_xor_sync(0xffffffffu, rmax1, 2));

        float mn0 = fmaxf(mx0, rmax0), mn1 = fmaxf(mx1, rmax1);
        float sc0 = __expf(mx0 - mn0), sc1 = __expf(mx1 - mn1);
        float rs0 = 0.f, rs1 = 0.f;
#pragma unroll
        for (int nt = 0; nt < 8; nt++) {
            sacc[nt][0] = __expf(sacc[nt][0] - mn0); rs0 += sacc[nt][0];
            sacc[nt][1] = __expf(sacc[nt][1] - mn0); rs0 += sacc[nt][1];
            sacc[nt][2] = __expf(sacc[nt][2] - mn1); rs1 += sacc[nt][2];
            sacc[nt][3] = __expf(sacc[nt][3] - mn1); rs1 += sacc[nt][3];
        }
        rs0 += __shfl_xor_sync(0xffffffffu, rs0, 1);
        rs0 += __shfl_xor_sync(0xffffffffu, rs0, 2);
        rs1 += __shfl_xor_sync(0xffffffffu, rs1, 1);
        rs1 += __shfl_xor_sync(0xffffffffu, rs1, 2);
        sum0 = sum0 * sc0 + rs0;  mx0 = mn0;
        sum1 = sum1 * sc1 + rs1;  mx1 = mn1;
#pragma unroll
        for (int vt = 0; vt < 8; vt++) {
            o[vt][0] *= sc0; o[vt][1] *= sc0;
            o[vt][2] *= sc1; o[vt][3] *= sc1;
        }

        // ---- O += P V^T : pack P from C-frags, 3-pass compensation ----
#pragma unroll
        for (int kt = 0; kt < 4; kt++) {
            const int t0 = 2 * kt, t1 = 2 * kt + 1;
            uint32_t ph[4], pl[4];
            ph[0] = bf16x2(sacc[t0][0], sacc[t0][1]);
            ph[1] = bf16x2(sacc[t0][2], sacc[t0][3]);
            ph[2] = bf16x2(sacc[t1][0], sacc[t1][1]);
            ph[3] = bf16x2(sacc[t1][2], sacc[t1][3]);
            pl[0] = bf16x2(sacc[t0][0] - bhi(sacc[t0][0]),
                           sacc[t0][1] - bhi(sacc[t0][1]));
            pl[1] = bf16x2(sacc[t0][2] - bhi(sacc[t0][2]),
                           sacc[t0][3] - bhi(sacc[t0][3]));
            pl[2] = bf16x2(sacc[t1][0] - bhi(sacc[t1][0]),
                           sacc[t1][1] - bhi(sacc[t1][1]));
            pl[3] = bf16x2(sacc[t1][2] - bhi(sacc[t1][2]),
                           sacc[t1][3] - bhi(sacc[t1][3]));

            uint32_t vf[8][2];
#pragma unroll
            for (int g = 0; g < 4; g++) {
                uint32_t off = SWB((uint32_t)((g * 16 + b_r) * 128 + kt * 32 + b_kb));
                LDSM4(vf[2 * g][0], vf[2 * g][1], vf[2 * g + 1][0], vf[2 * g + 1][1],
                      vhb + off);
            }
#pragma unroll
            for (int vt = 0; vt < 8; vt++) MMA16816(o[vt], ph, vf[vt]);
#pragma unroll
            for (int vt = 0; vt < 8; vt++) MMA16816(o[vt], pl, vf[vt]);
#pragma unroll
            for (int g = 0; g < 4; g++) {
                uint32_t off = SWB((uint32_t)((g * 16 + b_r) * 128 + kt * 32 + b_kb));
                LDSM4(vf[2 * g][0], vf[2 * g][1], vf[2 * g + 1][0], vf[2 * g + 1][1],
                      vlb + off);
            }
#pragma unroll
            for (int vt = 0; vt < 8; vt++) MMA16816(o[vt], ph, vf[vt]);
        }
    }

    // ---- normalize + write y in [b*L][h*64+v] layout ----
    {
        float inv0 = 1.f / sum0, inv1 = 1.f / sum1;
        int r0 = i * 64 + warp * 16 + (lane >> 2);
        int c0 = h * 64 + (lane & 3) * 2;
#pragma unroll
        for (int vt = 0; vt < 8; vt++) {
            int col = c0 + vt * 8;
            *(float2*)(g_y + (size_t)(b * SEQ + r0) * MODEL + col) =
                make_float2(o[vt][0] * inv0, o[vt][1] * inv0);
            *(float2*)(g_y + (size_t)(b * SEQ + r0 + 8) * MODEL + col) =
                make_float2(o[vt][2] * inv1, o[vt][3] * inv1);
        }
    }
}

// ---------------------------------------------------------------------------
extern "C" void kernel_launch(void* const* d_in, const int* in_sizes, int n_in,
                              void* d_out, int out_size)
{
    (void)in_sizes; (void)n_in; (void)out_size;
    const float* x    = (const float*)d_in[0];
    const float* w_q  = (const float*)d_in[1];
    const float* w_kv = (const float*)d_in[2];
    const float* w_o  = (const float*)d_in[3];
    const float* kw   = (const float*)d_in[4];
    float* out = (float*)d_out;

    cudaFuncSetAttribute(gemm_bf16<0>, cudaFuncAttributeMaxDynamicSharedMemorySize, GEMM_SMEM);
    cudaFuncSetAttribute(gemm_bf16<1>, cudaFuncAttributeMaxDynamicSharedMemorySize, GEMM_SMEM);
    cudaFuncSetAttribute(gemm_bf16<2>, cudaFuncAttributeMaxDynamicSharedMemorySize, GEMM_SMEM);

    dim3 ggrid(MODEL / 128, MROWS / 128);                    // (8, 32)

    wsplit_kernel<<<dim3(32, 32, 3), 256>>>(w_q, w_kv, w_o); // W^T hi/lo bf16
    gemm_bf16<1><<<ggrid, 256, GEMM_SMEM>>>(x, nullptr);     // q  -> g_q
    gemm_bf16<2><<<ggrid, 256, GEMM_SMEM>>>(x, nullptr);     // kv -> g_kv
    attn_tc<<<dim3(16, BATCH * HEADS), 128>>>(kw);           // -> g_y
    gemm_bf16<0><<<ggrid, 256, GEMM_SMEM>>>(nullptr, out);   // y @ w_o -> out
}

// round 11
// speedup vs baseline: 2.6610x; 1.1736x over previous
#include <cuda_runtime.h>
#include <cuda_bf16.h>
#include <cstdint>

// Shapes (fixed by the problem)
#define BATCH 4
#define SEQ   1024
#define MODEL 1024
#define HEADS 16
#define VDIM  64
#define MROWS (BATCH*SEQ)        // 4096 GEMM rows

// Scratch (device globals — no allocations allowed). All bf16 hi/lo pairs.
__device__ __align__(16) uint16_t g_xh[MROWS*MODEL], g_xl[MROWS*MODEL];  // x split
__device__ __align__(16) uint16_t g_wb_hi[3][MODEL*MODEL];               // W^T hi [n][k]
__device__ __align__(16) uint16_t g_wb_lo[3][MODEL*MODEL];               // W^T lo [n][k]
__device__ __align__(16) uint16_t g_qh[BATCH*HEADS*SEQ*VDIM], g_ql[BATCH*HEADS*SEQ*VDIM]; // q/32 [bh][l][v]
__device__ __align__(16) uint16_t g_kh[BATCH*HEADS*SEQ*VDIM], g_kl[BATCH*HEADS*SEQ*VDIM]; // kv*(1+kw)
__device__ __align__(16) uint16_t g_vh[BATCH*HEADS*SEQ*VDIM], g_vl[BATCH*HEADS*SEQ*VDIM]; // kv
__device__ __align__(16) uint16_t g_vth[BATCH*HEADS*SEQ*VDIM], g_vtl[BATCH*HEADS*SEQ*VDIM]; // V^T [bh][v][l]
__device__ __align__(16) uint16_t g_yh[MROWS*MODEL], g_yl[MROWS*MODEL];  // y split

// ---------------------------------------------------------------------------
// Helpers (family-portable PTX only: ldmatrix + mma.sync + cp.async, sm_80)
// ---------------------------------------------------------------------------
__device__ __forceinline__ uint32_t smem_u32(const void* p) {
    uint32_t a;
    asm("{ .reg .u64 t; cvta.to.shared.u64 t, %1; cvt.u32.u64 %0, t; }"
        : "=r"(a) : "l"(p));
    return a;
}
__device__ __forceinline__ uint32_t bf16x2(float e0, float e1) {   // e0 = low half
    uint32_t r;
    asm("cvt.rn.bf16x2.f32 %0, %1, %2;" : "=r"(r) : "f"(e1), "f"(e0));
    return r;
}
__device__ __forceinline__ void bsplit(float a, float& h, float& l) {
    h = __bfloat162float(__float2bfloat16_rn(a));
    l = a - h;
}
__device__ __forceinline__ float bhi(float a) {
    return __bfloat162float(__float2bfloat16_rn(a));
}
__device__ __forceinline__ void cpa16(uint32_t s, const void* g) {
    asm volatile("cp.async.cg.shared.global [%0], [%1], 16;" :: "r"(s), "l"(g) : "memory");
}
#define CP_COMMIT() asm volatile("cp.async.commit_group;" ::: "memory")
#define CP_WAIT0()  asm volatile("cp.async.wait_group 0;" ::: "memory")
#define SWB(b) ((b) ^ (((b) >> 3) & 0x70))       // SW128 XOR swizzle (128B rows)

#define LDSM4(r0, r1, r2, r3, addr) \
    asm volatile("ldmatrix.sync.aligned.m8n8.x4.shared.b16 {%0,%1,%2,%3}, [%4];" \
        : "=r"(r0), "=r"(r1), "=r"(r2), "=r"(r3) : "r"(addr))

#define MMA16816(C, A, B) \
    asm volatile("mma.sync.aligned.m16n8k16.row.col.f32.bf16.bf16.f32 " \
        "{%0,%1,%2,%3},{%4,%5,%6,%7},{%8,%9},{%0,%1,%2,%3};" \
        : "+f"((C)[0]), "+f"((C)[1]), "+f"((C)[2]), "+f"((C)[3]) \
        : "r"((A)[0]), "r"((A)[1]), "r"((A)[2]), "r"((A)[3]), \
          "r"((B)[0]), "r"((B)[1]))

// ---------------------------------------------------------------------------
// Weight transpose + bf16 hi/lo split: W[k][n] -> Wt_hi/lo[n][k] (3 weights)
// ---------------------------------------------------------------------------
__global__ void __launch_bounds__(256)
wsplit_kernel(const float* __restrict__ w0, const float* __restrict__ w1,
              const float* __restrict__ w2)
{
    __shared__ float s[32][33];
    const int z = blockIdx.z;
    const float* src = (z == 0) ? w0 : (z == 1) ? w1 : w2;
    uint16_t* dh = g_wb_hi[z];
    uint16_t* dl = g_wb_lo[z];
    const int kt = blockIdx.x * 32, nt = blockIdx.y * 32;
    const int f = threadIdx.x;
    const int r = f >> 3, c4 = f & 7;

    float4 v = *(const float4*)(src + (size_t)(kt + r) * MODEL + nt + c4 * 4);
    s[r][c4 * 4 + 0] = v.x; s[r][c4 * 4 + 1] = v.y;
    s[r][c4 * 4 + 2] = v.z; s[r][c4 * 4 + 3] = v.w;
    __syncthreads();

    float hh[4], ll[4];
#pragma unroll
    for (int q = 0; q < 4; q++) bsplit(s[c4 * 4 + q][r], hh[q], ll[q]);

    size_t off = (size_t)(nt + r) * MODEL + kt + c4 * 4;
    *(uint2*)(dh + off) = make_uint2(bf16x2(hh[0], hh[1]), bf16x2(hh[2], hh[3]));
    *(uint2*)(dl + off) = make_uint2(bf16x2(ll[0], ll[1]), bf16x2(ll[2], ll[3]));
}

// ---------------------------------------------------------------------------
// X -> bf16 hi/lo split (once)
// ---------------------------------------------------------------------------
__global__ void __launch_bounds__(256)
xsplit_kernel(const float* __restrict__ x)
{
    int e = (blockIdx.x * 256 + threadIdx.x) * 4;
    float4 v = *(const float4*)(x + e);
    float h0, l0, h1, l1, h2, l2, h3, l3;
    bsplit(v.x, h0, l0); bsplit(v.y, h1, l1);
    bsplit(v.z, h2, l2); bsplit(v.w, h3, l3);
    *(uint2*)(g_xh + e) = make_uint2(bf16x2(h0, h1), bf16x2(h2, h3));
    *(uint2*)(g_xl + e) = make_uint2(bf16x2(l0, l1), bf16x2(l2, l3));
}

// ---------------------------------------------------------------------------
// V [bh][l][v] -> V^T [bh][v][l] (hi and lo), 64x64 smem tile transpose
// ---------------------------------------------------------------------------
__global__ void __launch_bounds__(128)
vtprep_kernel()
{
    __shared__ uint16_t t[64][65];
    const int bh = blockIdx.y, l0 = blockIdx.x * 64;
    const int tid = threadIdx.x;
#pragma unroll
    for (int arr = 0; arr < 2; arr++) {
        const uint16_t* src = arr ? g_vl : g_vh;
        uint16_t* dst = arr ? g_vtl : g_vth;
        if (arr) __syncthreads();
#pragma unroll
        for (int it = 0; it < 4; it++) {
            int e = (tid + it * 128) * 8;
            int l = e >> 6, v = e & 63;
            uint4 u = *(const uint4*)(src + ((size_t)bh * SEQ + l0 + l) * VDIM + v);
            const uint16_t* up = (const uint16_t*)&u;
#pragma unroll
            for (int q = 0; q < 8; q++) t[l][v + q] = up[q];
        }
        __syncthreads();
#pragma unroll
        for (int it = 0; it < 4; it++) {
            int e = (tid + it * 128) * 8;
            int v = e >> 6, l = e & 63;
            uint16_t buf[8];
#pragma unroll
            for (int q = 0; q < 8; q++) buf[q] = t[l + q][v];
            *(uint4*)(dst + ((size_t)bh * VDIM + v) * SEQ + l0 + l) = *(uint4*)buf;
        }
    }
}

// ---------------------------------------------------------------------------
// Pure-bf16 3-pass GEMM, cp.async loads (A and B pre-split in gmem).
// C[4096,1024] = A @ W. CTA 128x128x64, 8 warps, warp 64x32.
// MODE 0: A=y  -> OUT fp32.  MODE 1: A=x -> q (x1/32, split, [bh][l][v]).
// MODE 2: A=x -> k=(kv*(1+kw)) split + v=kv split, [bh][l][v].
// ---------------------------------------------------------------------------
#define SA_HI 0
#define SA_LO 16384
#define SB_HI 32768
#define SB_LO 49152
#define GEMM_SMEM 65536

template<int MODE>
__global__ void __launch_bounds__(256)
gemm2(const float* __restrict__ kw_g, float* __restrict__ OUT)
{
    extern __shared__ __align__(1024) char smem[];
    const uint32_t sb = smem_u32(smem);

    const uint16_t* __restrict__ Ah = (MODE == 0) ? g_yh : g_xh;
    const uint16_t* __restrict__ Al = (MODE == 0) ? g_yl : g_xl;
    const int widx = (MODE == 1) ? 0 : (MODE == 2) ? 1 : 2;
    const uint16_t* __restrict__ Bh = g_wb_hi[widx];
    const uint16_t* __restrict__ Bl = g_wb_lo[widx];

    const int tid  = threadIdx.x;
    const int lane = tid & 31, wid = tid >> 5;
    const int warp_m = wid & 1;
    const int warp_n = wid >> 1;
    const int m0 = blockIdx.y * 128, n0 = blockIdx.x * 128;

    const int a_r  = lane & 15;
    const int a_kb = (lane >> 4) * 16;
    const int b_r  = (lane & 7) | ((lane & 16) >> 1);
    const int b_kb = (lane & 8) * 2;

    float c[4][4][4];
#pragma unroll
    for (int mt = 0; mt < 4; mt++)
#pragma unroll
        for (int nt = 0; nt < 4; nt++)
#pragma unroll
            for (int q = 0; q < 4; q++) c[mt][nt][q] = 0.f;

    for (int kc = 0; kc < 16; kc++) {
        if (kc) __syncthreads();
#pragma unroll
        for (int i = 0; i < 4; i++) {
            int e = (tid + i * 256) * 8;
            int row = e >> 6, k = e & 63;
            uint32_t off = SWB((uint32_t)(row * 128 + k * 2));
            size_t ga = (size_t)(m0 + row) * MODEL + kc * 64 + k;
            size_t gb = (size_t)(n0 + row) * MODEL + kc * 64 + k;
            cpa16(sb + SA_HI + off, Ah + ga);
            cpa16(sb + SA_LO + off, Al + ga);
            cpa16(sb + SB_HI + off, Bh + gb);
            cpa16(sb + SB_LO + off, Bl + gb);
        }
        CP_COMMIT();
        CP_WAIT0();
        __syncthreads();

#pragma unroll
        for (int p = 0; p < 3; p++) {
            const uint32_t Ab = sb + ((p == 2) ? SA_LO : SA_HI);
            const uint32_t Bb = sb + ((p == 1) ? SB_LO : SB_HI);
#pragma unroll
            for (int ks = 0; ks < 4; ks++) {
                uint32_t a[4][4], b[4][2];
#pragma unroll
                for (int mt = 0; mt < 4; mt++) {
                    uint32_t ad = Ab + SWB((uint32_t)(
                        (warp_m * 64 + mt * 16 + a_r) * 128 + ks * 32 + a_kb));
                    LDSM4(a[mt][0], a[mt][1], a[mt][2], a[mt][3], ad);
                }
#pragma unroll
                for (int bt = 0; bt < 2; bt++) {
                    uint32_t bd = Bb + SWB((uint32_t)(
                        (warp_n * 32 + bt * 16 + b_r) * 128 + ks * 32 + b_kb));
                    LDSM4(b[2 * bt][0], b[2 * bt][1],
                          b[2 * bt + 1][0], b[2 * bt + 1][1], bd);
                }
#pragma unroll
                for (int mt = 0; mt < 4; mt++)
#pragma unroll
                    for (int nt = 0; nt < 4; nt++)
                        MMA16816(c[mt][nt], a[mt], b[nt]);
            }
        }
    }

    const int gr = lane >> 2, gc = (lane & 3) * 2;
#pragma unroll
    for (int mt = 0; mt < 4; mt++) {
#pragma unroll
        for (int nt = 0; nt < 4; nt++) {
            int col = n0 + warp_n * 32 + nt * 8 + gc;
#pragma unroll
            for (int half = 0; half < 2; half++) {
                int rr = m0 + warp_m * 64 + mt * 16 + gr + half * 8;
                float vx = c[mt][nt][half * 2], vy = c[mt][nt][half * 2 + 1];
                if (MODE == 0) {
                    *(float2*)(OUT + (size_t)rr * MODEL + col) = make_float2(vx, vy);
                } else {
                    int hh = col >> 6, v = col & 63;
                    int b = rr >> 10, l = rr & 1023;
                    size_t o = ((size_t)((b * HEADS + hh) * SEQ + l)) * VDIM + v;
                    float xh, xl, yh, yl;
                    if (MODE == 1) {
                        vx *= 0.03125f; vy *= 0.03125f;
                        bsplit(vx, xh, xl); bsplit(vy, yh, yl);
                        *(uint32_t*)(g_qh + o) = bf16x2(xh, yh);
                        *(uint32_t*)(g_ql + o) = bf16x2(xl, yl);
                    } else {
                        float2 w = *(const float2*)(kw_g + hh * 64 + v);
                        bsplit(vx * (1.f + w.x), xh, xl);
                        bsplit(vy * (1.f + w.y), yh, yl);
                        *(uint32_t*)(g_kh + o) = bf16x2(xh, yh);
                        *(uint32_t*)(g_kl + o) = bf16x2(xl, yl);
                        bsplit(vx, xh, xl); bsplit(vy, yh, yl);
                        *(uint32_t*)(g_vh + o) = bf16x2(xh, yh);
                        *(uint32_t*)(g_vl + o) = bf16x2(xl, yl);
                    }
                }
            }
        }
    }
}

// ---------------------------------------------------------------------------
// Tensor-core flash attention. All operands pre-split bf16 in gmem; K/V tiles
// double-buffered via cp.async. CTA = (bh, 64-query block), 4 warps.
// smem: Q hi/lo 16KB + 2 stages x (Kh,Kl,Vth,Vtl 8KB each) = 80KB dynamic.
// ---------------------------------------------------------------------------
#define AQ_H 0
#define AQ_L 8192
#define AST(s) (16384 + (s) * 32768)
#define AK_H 0
#define AK_L 8192
#define AV_H 16384
#define AV_L 24576
#define ATTN_SMEM (16384 + 2 * 32768)

__global__ void __launch_bounds__(128)
attn2()
{
    extern __shared__ __align__(1024) char smem[];
    const uint32_t sb = smem_u32(smem);

    const int tid = threadIdx.x, lane = tid & 31, warp = tid >> 5;
    const int i  = 15 - blockIdx.x;          // heavy diagonal blocks first
    const int bh = blockIdx.y;
    const int hd = bh & (HEADS - 1);
    const int b  = bh >> 4;

    const int a_r  = lane & 15;
    const int a_kb = (lane >> 4) * 16;
    const int b_r  = (lane & 7) | ((lane & 16) >> 1);
    const int b_kb = (lane & 8) * 2;

    // ---- Q tile: straight copy of pre-split bf16 ----
    {
        const uint16_t* qh_g = g_qh + ((size_t)bh * SEQ + i * 64) * VDIM;
        const uint16_t* ql_g = g_ql + ((size_t)bh * SEQ + i * 64) * VDIM;
#pragma unroll
        for (int it = 0; it < 4; it++) {
            int e = (tid + it * 128) * 8;
            int row = e >> 6, k = e & 63;
            uint32_t off = SWB((uint32_t)(row * 128 + k * 2));
            *(uint4*)(smem + AQ_H + off) = *(const uint4*)(qh_g + row * 64 + k);
            *(uint4*)(smem + AQ_L + off) = *(const uint4*)(ql_g + row * 64 + k);
        }
    }

    // ---- prefetch K/V stage 0 ----
    const uint16_t* kh_b = g_kh + (size_t)bh * SEQ * VDIM;
    const uint16_t* kl_b = g_kl + (size_t)bh * SEQ * VDIM;
    const uint16_t* vth_b = g_vth + (size_t)bh * VDIM * SEQ;
    const uint16_t* vtl_b = g_vtl + (size_t)bh * VDIM * SEQ;
    auto issue_kv = [&](int s, int j) {
        uint32_t base = sb + AST(s);
#pragma unroll
        for (int it = 0; it < 4; it++) {
            int e = (tid + it * 128) * 8;
            int row = e >> 6, k = e & 63;
            uint32_t off = SWB((uint32_t)(row * 128 + k * 2));
            cpa16(base + AK_H + off, kh_b + (size_t)(j * 64 + row) * VDIM + k);
            cpa16(base + AK_L + off, kl_b + (size_t)(j * 64 + row) * VDIM + k);
            cpa16(base + AV_H + off, vth_b + (size_t)row * SEQ + j * 64 + k);
            cpa16(base + AV_L + off, vtl_b + (size_t)row * SEQ + j * 64 + k);
        }
    };
    issue_kv(0, 0);
    CP_COMMIT();
    __syncthreads();   // Q smem visible to all warps

    // ---- preload Q A-fragments (resident) ----
    uint32_t qh[4][4], ql[4][4];
#pragma unroll
    for (int ks = 0; ks < 4; ks++) {
        uint32_t off = SWB((uint32_t)((warp * 16 + a_r) * 128 + ks * 32 + a_kb));
        LDSM4(qh[ks][0], qh[ks][1], qh[ks][2], qh[ks][3], sb + AQ_H + off);
        LDSM4(ql[ks][0], ql[ks][1], ql[ks][2], ql[ks][3], sb + AQ_L + off);
    }

    float o[8][4];
#pragma unroll
    for (int vt = 0; vt < 8; vt++)
#pragma unroll
        for (int q = 0; q < 4; q++) o[vt][q] = 0.f;
    float mx0 = -1e30f, mx1 = -1e30f, sum0 = 0.f, sum1 = 0.f;

    for (int j = 0; j <= i; j++) {
        CP_WAIT0();
        __syncthreads();   // stage j ready; all warps done with stage j-1
        if (j < i) { issue_kv((j + 1) & 1, j + 1); CP_COMMIT(); }

        const uint32_t khb = sb + AST(j & 1) + AK_H;
        const uint32_t klb = sb + AST(j & 1) + AK_L;
        const uint32_t vhb = sb + AST(j & 1) + AV_H;
        const uint32_t vlb = sb + AST(j & 1) + AV_L;

        // ---- S = Q K^T : 3-pass compensation ----
        float sacc[8][4];
#pragma unroll
        for (int nt = 0; nt < 8; nt++)
#pragma unroll
            for (int q = 0; q < 4; q++) sacc[nt][q] = 0.f;

#pragma unroll
        for (int ks = 0; ks < 4; ks++) {
            uint32_t kf[8][2];
#pragma unroll
            for (int g = 0; g < 4; g++) {
                uint32_t off = SWB((uint32_t)((g * 16 + b_r) * 128 + ks * 32 + b_kb));
                LDSM4(kf[2 * g][0], kf[2 * g][1], kf[2 * g + 1][0], kf[2 * g + 1][1],
                      khb + off);
            }
#pragma unroll
            for (int nt = 0; nt < 8; nt++) MMA16816(sacc[nt], qh[ks], kf[nt]);
#pragma unroll
            for (int nt = 0; nt < 8; nt++) MMA16816(sacc[nt], ql[ks], kf[nt]);
#pragma unroll
            for (int g = 0; g < 4; g++) {
                uint32_t off = SWB((uint32_t)((g * 16 + b_r) * 128 + ks * 32 + b_kb));
                LDSM4(kf[2 * g][0], kf[2 * g][1], kf[2 * g + 1][0], kf[2 * g + 1][1],
                      klb + off);
            }
#pragma unroll
            for (int nt = 0; nt < 8; nt++) MMA16816(sacc[nt], qh[ks], kf[nt]);
        }

        // ---- causal mask on diagonal tile ----
        if (j == i) {
            int r0 = warp * 16 + (lane >> 2);
            int c0 = (lane & 3) * 2;
#pragma unroll
            for (int nt = 0; nt < 8; nt++) {
                int col = nt * 8 + c0;
                if (col     > r0)     sacc[nt][0] = -1e30f;
                if (col + 1 > r0)     sacc[nt][1] = -1e30f;
                if (col     > r0 + 8) sacc[nt][2] = -1e30f;
                if (col + 1 > r0 + 8) sacc[nt][3] = -1e30f;
            }
        }

        // ---- online softmax in fragment registers ----
        float rmax0 = -1e30f, rmax1 = -1e30f;
#pragma unroll
        for (int nt = 0; nt < 8; nt++) {
            rmax0 = fmaxf(rmax0, fmaxf(sacc[nt][0], sacc[nt][1]));
            rmax1 = fmaxf(rmax1, fmaxf(sacc[nt][2], sacc[nt][3]));
        }
        rmax0 = fmaxf(rmax0, __shfl_xor_sync(0xffffffffu, rmax0, 1));
        rmax0 = fmaxf(rmax0, __shfl_xor_sync(0xffffffffu, rmax0, 2));
        rmax1 = fmaxf(rmax1, __shfl_xor_sync(0xffffffffu, rmax1, 1));
        rmax1 = fmaxf(rmax1, __shfl_xor_sync(0xffffffffu, rmax1, 2));

        float mn0 = fmaxf(mx0, rmax0), mn1 = fmaxf(mx1, rmax1);
        float sc0 = __expf(mx0 - mn0), sc1 = __expf(mx1 - mn1);
        float rs0 = 0.f, rs1 = 0.f;
#pragma unroll
        for (int nt = 0; nt < 8; nt++) {
            sacc[nt][0] = __expf(sacc[nt][0] - mn0); rs0 += sacc[nt][0];
            sacc[nt][1] = __expf(sacc[nt][1] - mn0); rs0 += sacc[nt][1];
            sacc[nt][2] = __expf(sacc[nt][2] - mn1); rs1 += sacc[nt][2];
            sacc[nt][3] = __expf(sacc[nt][3] - mn1); rs1 += sacc[nt][3];
        }
        rs0 += __shfl_xor_sync(0xffffffffu, rs0, 1);
        rs0 += __shfl_xor_sync(0xffffffffu, rs0, 2);
        rs1 += __shfl_xor_sync(0xffffffffu, rs1, 1);
        rs1 += __shfl_xor_sync(0xffffffffu, rs1, 2);
        sum0 = sum0 * sc0 + rs0;  mx0 = mn0;
        sum1 = sum1 * sc1 + rs1;  mx1 = mn1;
#pragma unroll
        for (int vt = 0; vt < 8; vt++) {
            o[vt][0] *= sc0; o[vt][1] *= sc0;
            o[vt][2] *= sc1; o[vt][3] *= sc1;
        }

        // ---- O += P V^T : pack P from C-frags, 3-pass compensation ----
#pragma unroll
        for (int kt = 0; kt < 4; kt++) {
            const int t0 = 2 * kt, t1 = 2 * kt + 1;
            uint32_t ph[4], pl[4];
            ph[0] = bf16x2(sacc[t0][0], sacc[t0][1]);
            ph[1] = bf16x2(sacc[t0][2], sacc[t0][3]);
            ph[2] = bf16x2(sacc[t1][0], sacc[t1][1]);
            ph[3] = bf16x2(sacc[t1][2], sacc[t1][3]);
            pl[0] = bf16x2(sacc[t0][0] - bhi(sacc[t0][0]),
                           sacc[t0][1] - bhi(sacc[t0][1]));
            pl[1] = bf16x2(sacc[t0][2] - bhi(sacc[t0][2]),
                           sacc[t0][3] - bhi(sacc[t0][3]));
            pl[2] = bf16x2(sacc[t1][0] - bhi(sacc[t1][0]),
                           sacc[t1][1] - bhi(sacc[t1][1]));
            pl[3] = bf16x2(sacc[t1][2] - bhi(sacc[t1][2]),
                           sacc[t1][3] - bhi(sacc[t1][3]));

            uint32_t vf[8][2];
#pragma unroll
            for (int g = 0; g < 4; g++) {
                uint32_t off = SWB((uint32_t)((g * 16 + b_r) * 128 + kt * 32 + b_kb));
                LDSM4(vf[2 * g][0], vf[2 * g][1], vf[2 * g + 1][0], vf[2 * g + 1][1],
                      vhb + off);
            }
#pragma unroll
            for (int vt = 0; vt < 8; vt++) MMA16816(o[vt], ph, vf[vt]);
#pragma unroll
            for (int vt = 0; vt < 8; vt++) MMA16816(o[vt], pl, vf[vt]);
#pragma unroll
            for (int g = 0; g < 4; g++) {
                uint32_t off = SWB((uint32_t)((g * 16 + b_r) * 128 + kt * 32 + b_kb));
                LDSM4(vf[2 * g][0], vf[2 * g][1], vf[2 * g + 1][0], vf[2 * g + 1][1],
                      vlb + off);
            }
#pragma unroll
            for (int vt = 0; vt < 8; vt++) MMA16816(o[vt], ph, vf[vt]);
        }
    }

    // ---- normalize + write y pre-split bf16 in [b*L][h*64+v] layout ----
    {
        float inv0 = 1.f / sum0, inv1 = 1.f / sum1;
        int r0 = i * 64 + warp * 16 + (lane >> 2);
        int c0 = hd * 64 + (lane & 3) * 2;
#pragma unroll
        for (int vt = 0; vt < 8; vt++) {
            int col = c0 + vt * 8;
            float y0 = o[vt][0] * inv0, y1 = o[vt][1] * inv0;
            float h0, l0, h1, l1;
            bsplit(y0, h0, l0); bsplit(y1, h1, l1);
            size_t off0 = (size_t)(b * SEQ + r0) * MODEL + col;
            *(uint32_t*)(g_yh + off0) = bf16x2(h0, h1);
            *(uint32_t*)(g_yl + off0) = bf16x2(l0, l1);
            y0 = o[vt][2] * inv1; y1 = o[vt][3] * inv1;
            bsplit(y0, h0, l0); bsplit(y1, h1, l1);
            size_t off1 = (size_t)(b * SEQ + r0 + 8) * MODEL + col;
            *(uint32_t*)(g_yh + off1) = bf16x2(h0, h1);
            *(uint32_t*)(g_yl + off1) = bf16x2(l0, l1);
        }
    }
}

// ---------------------------------------------------------------------------
extern "C" void kernel_launch(void* const* d_in, const int* in_sizes, int n_in,
                              void* d_out, int out_size)
{
    (void)in_sizes; (void)n_in; (void)out_size;
    const float* x    = (const float*)d_in[0];
    const float* w_q  = (const float*)d_in[1];
    const float* w_kv = (const float*)d_in[2];
    const float* w_o  = (const float*)d_in[3];
    const float* kw   = (const float*)d_in[4];
    float* out = (float*)d_out;

    cudaFuncSetAttribute(gemm2<0>, cudaFuncAttributeMaxDynamicSharedMemorySize, GEMM_SMEM);
    cudaFuncSetAttribute(gemm2<1>, cudaFuncAttributeMaxDynamicSharedMemorySize, GEMM_SMEM);
    cudaFuncSetAttribute(gemm2<2>, cudaFuncAttributeMaxDynamicSharedMemorySize, GEMM_SMEM);
    cudaFuncSetAttribute(attn2, cudaFuncAttributeMaxDynamicSharedMemorySize, ATTN_SMEM);

    dim3 ggrid(MODEL / 128, MROWS / 128);                    // (8, 32)

    wsplit_kernel<<<dim3(32, 32, 3), 256>>>(w_q, w_kv, w_o); // W^T hi/lo bf16
    xsplit_kernel<<<MROWS * MODEL / 1024, 256>>>(x);         // x hi/lo bf16
    gemm2<1><<<ggrid, 256, GEMM_SMEM>>>(nullptr, nullptr);   // q  (split)
    gemm2<2><<<ggrid, 256, GEMM_SMEM>>>(kw, nullptr);        // k (scaled) + v (split)
    vtprep_kernel<<<dim3(16, BATCH * HEADS), 128>>>();       // V^T hi/lo
    attn2<<<dim3(16, BATCH * HEADS), 128, ATTN_SMEM>>>();    // -> y (split)
    gemm2<0><<<ggrid, 256, GEMM_SMEM>>>(nullptr, out);       // y @ w_o -> out
}